// round 9
// baseline (speedup 1.0000x reference)
#include <cuda_runtime.h>
#include <cuda_bf16.h>
#include <cstdint>
#include <math.h>

// ===========================================================================
// MultiScaleBlock (sm_103 PTX, HMMA mma.sync path).
// Window-major pixel permutation: row = (((b*32+wi)*32+wj)*16 + t2)*4 + dq.
// Fused proj+qkv GEMM with maxpool fused in epilogue.
// Precision tiers: proj/attn-proj/mlp GEMMs bf16x3 (hi/lo); qkv tiles bf16x1.
// GEMM: 2-stage cp.async pipeline, 2 CTAs/SM (occupancy-bound fix, R9).
// Attention: bf16x2-packed smem + 4x4 register blocking, all heads parallel.
// ===========================================================================

#define NPIX   (4*256*256)     // 262144
#define NPOOL  (4*128*128)     // 65536
#define NWIN   (4*32*32)       // 4096

// ---------------- scratch (device globals) ----------------------------------
__device__ __nv_bfloat16 g_xh [(size_t)NPIX  * 96];
__device__ __nv_bfloat16 g_xl [(size_t)NPIX  * 96];
__device__ __nv_bfloat16 g_qkvb[(size_t)NPIX * 576];     // bf16 qkv, window-major
__device__ __nv_bfloat16 g_oh [(size_t)NPOOL * 192];
__device__ __nv_bfloat16 g_ol [(size_t)NPOOL * 192];
__device__ __nv_bfloat16 g_ynh[(size_t)NPOOL * 192];
__device__ __nv_bfloat16 g_ynl[(size_t)NPOOL * 192];
__device__ __nv_bfloat16 g_hh [(size_t)NPOOL * 768];
__device__ __nv_bfloat16 g_hl [(size_t)NPOOL * 768];
// weights [N][K] bf16 hi/lo (transposed); proj+qkv fused into 768 rows
__device__ __nv_bfloat16 g_wfh[768*96],  g_wfl[768*96];
__device__ __nv_bfloat16 g_wah[192*192], g_wal[192*192];
__device__ __nv_bfloat16 g_w1h[768*192], g_w1l[768*192];
__device__ __nv_bfloat16 g_w2h[192*768], g_w2l[192*768];
__device__ float         g_b768[768];

// ---------------- helpers ---------------------------------------------------
__device__ __forceinline__ uint32_t smem_u32(const void* p) {
    uint32_t a;
    asm("{ .reg .u64 t; cvta.to.shared.u64 t, %1; cvt.u32.u64 %0, t; }"
        : "=r"(a) : "l"(p));
    return a;
}
__device__ __forceinline__ void cp16(uint32_t s, const void* g) {
    asm volatile("cp.async.ca.shared.global [%0], [%1], 16;"
                 :: "r"(s), "l"(g) : "memory");
}
__device__ __forceinline__ void cp_commit() {
    asm volatile("cp.async.commit_group;" ::: "memory");
}
template<int N>
__device__ __forceinline__ void cp_wait() {
    asm volatile("cp.async.wait_group %0;" :: "n"(N) : "memory");
}
__device__ __forceinline__ void ldsm4(uint32_t* r, uint32_t a) {
    asm volatile("ldmatrix.sync.aligned.m8n8.x4.shared.b16 {%0,%1,%2,%3}, [%4];"
        : "=r"(r[0]), "=r"(r[1]), "=r"(r[2]), "=r"(r[3]) : "r"(a));
}
__device__ __forceinline__ void mma_bf16(float* d, const uint32_t* a,
                                         uint32_t b0, uint32_t b1) {
    asm volatile(
        "mma.sync.aligned.m16n8k16.row.col.f32.bf16.bf16.f32 "
        "{%0,%1,%2,%3}, {%4,%5,%6,%7}, {%8,%9}, {%0,%1,%2,%3};"
        : "+f"(d[0]), "+f"(d[1]), "+f"(d[2]), "+f"(d[3])
        : "r"(a[0]), "r"(a[1]), "r"(a[2]), "r"(a[3]), "r"(b0), "r"(b1));
}
__device__ __forceinline__ void split_bf16(float v, __nv_bfloat16& h, __nv_bfloat16& l) {
    h = __float2bfloat16(v);
    l = __float2bfloat16(v - __bfloat162float(h));
}
__device__ __forceinline__ float gelu_exact(float v) {
    return 0.5f * v * (1.0f + erff(v * 0.70710678118654752f));
}
// window-major quad index -> standard pooled row
__device__ __forceinline__ size_t quad_to_prow(size_t g) {
    int t2 = (int)(g & 15);
    int wj = (int)((g >> 4) & 31);
    int wi = (int)((g >> 9) & 31);
    int b  = (int)(g >> 14);
    return ((size_t)(b * 128 + wi * 4 + (t2 >> 2))) * 128 + wj * 4 + (t2 & 3);
}

// ---------------- HMMA GEMM, BM=128 BN=192 BK=32, 2-stage, 2 CTA/SM ---------
// x3 CTAs: hi/lo x3-product (2^-17); x1 CTAs (qkv tiles): hi-only (bf16).
#define LDA     40                         // BK + 8 (half-words)
#define SA_HI   0
#define SA_LO   (128*LDA*2)                // 10240
#define SB_HI   (2*128*LDA*2)              // 20480
#define SB_LO   (SB_HI + 192*LDA*2)        // 35840
#define STAGE_B (SB_LO + 192*LDA*2)        // 51200
#define GEMM_SMEM (2*STAGE_B)              // 102400

__global__ __launch_bounds__(256, 2) void gemm_mma(
    const __nv_bfloat16* __restrict__ Ah, const __nv_bfloat16* __restrict__ Al,
    const __nv_bfloat16* __restrict__ Bh, const __nv_bfloat16* __restrict__ Bl,
    int K, int N, int epi,
    const float* __restrict__ bias,
    float* __restrict__ Cf,
    __nv_bfloat16* __restrict__ Ch, __nv_bfloat16* __restrict__ Cl,
    const float* __restrict__ addsrc)
{
    extern __shared__ char smem[];
    const uint32_t sb = smem_u32(smem);
    const int tid = threadIdx.x, lane = tid & 31, warp = tid >> 5;
    const int wm = (warp >> 1) * 32;           // 4 warps in M
    const int wn = (warp & 1) * 96;            // 2 warps in N
    const size_t bm = (size_t)blockIdx.y * 128;
    const size_t bn = (size_t)blockIdx.x * 192;
    const int C = K >> 5;
    const bool x3 = !(epi == 3 && blockIdx.x != 0);   // qkv tiles: bf16x1

    const __nv_bfloat16* AhB = Ah + bm * K;
    const __nv_bfloat16* AlB = Al + bm * K;
    const __nv_bfloat16* BhB = Bh + bn * K;
    const __nv_bfloat16* BlB = Bl + bn * K;

    float acc[2][12][4];
    #pragma unroll
    for (int i = 0; i < 2; i++)
        #pragma unroll
        for (int j = 0; j < 12; j++)
            #pragma unroll
            for (int q = 0; q < 4; q++) acc[i][j][q] = 0.f;

    auto load_stage = [&](int s, int c) {
        const uint32_t st = sb + (uint32_t)s * STAGE_B;
        const size_t k0 = (size_t)c * 32;
        #pragma unroll
        for (int i = tid; i < 512; i += 256) {       // A: 128 rows x 4 chunks
            int r = i >> 2, q = i & 3;
            uint32_t d = st + (uint32_t)(r * LDA + q * 8) * 2;
            size_t go = (size_t)r * K + k0 + q * 8;
            cp16(d + SA_HI, AhB + go);
            if (x3) cp16(d + SA_LO, AlB + go);
        }
        #pragma unroll
        for (int i = tid; i < 768; i += 256) {       // B: 192 rows x 4 chunks
            int r = i >> 2, q = i & 3;
            uint32_t d = st + (uint32_t)(r * LDA + q * 8) * 2;
            size_t go = (size_t)r * K + k0 + q * 8;
            cp16(d + SB_HI, BhB + go);
            if (x3) cp16(d + SB_LO, BlB + go);
        }
        cp_commit();
    };

    auto compute_stage = [&](int s) {
        const uint32_t st = sb + (uint32_t)s * STAGE_B;
        #pragma unroll
        for (int k16 = 0; k16 < 2; k16++) {
            uint32_t ah[2][4], al[2][4];
            #pragma unroll
            for (int mi = 0; mi < 2; mi++) {
                int row = wm + mi * 16 + (lane & 15);
                int col = k16 * 16 + (lane >> 4) * 8;
                uint32_t ad = st + (uint32_t)(row * LDA + col) * 2;
                ldsm4(ah[mi], ad + SA_HI);
                if (x3) ldsm4(al[mi], ad + SA_LO);
            }
            #pragma unroll
            for (int ng = 0; ng < 6; ng++) {
                uint32_t bh[4], bl[4];
                int nr = wn + ng * 16 + (lane & 7) + ((lane >> 4) & 1) * 8;
                int bc = k16 * 16 + ((lane >> 3) & 1) * 8;
                uint32_t bd = st + (uint32_t)(nr * LDA + bc) * 2;
                ldsm4(bh, bd + SB_HI);
                if (x3) ldsm4(bl, bd + SB_LO);
                #pragma unroll
                for (int mi = 0; mi < 2; mi++) {
                    #pragma unroll
                    for (int sub = 0; sub < 2; sub++) {
                        float* d = acc[mi][ng * 2 + sub];
                        mma_bf16(d, ah[mi], bh[2*sub], bh[2*sub+1]);
                        if (x3) {
                            mma_bf16(d, ah[mi], bl[2*sub], bl[2*sub+1]);
                            mma_bf16(d, al[mi], bh[2*sub], bh[2*sub+1]);
                        }
                    }
                }
            }
        }
    };

    // ---- 2-stage pipeline ----
    load_stage(0, 0);
    for (int c = 0; c < C; c++) {
        if (c + 1 < C) {
            load_stage((c + 1) & 1, c + 1);
            cp_wait<1>();
        } else {
            cp_wait<0>();
        }
        __syncthreads();
        compute_stage(c & 1);
        __syncthreads();
    }

    // ---- epilogue ----
    #pragma unroll
    for (int mi = 0; mi < 2; mi++) {
        #pragma unroll
        for (int nj = 0; nj < 12; nj++) {
            size_t row0 = bm + wm + mi * 16 + (lane >> 2);
            size_t col  = bn + wn + nj * 8 + 2 * (lane & 3);
            float b0 = bias[col], b1 = bias[col + 1];
            float v00 = acc[mi][nj][0] + b0, v01 = acc[mi][nj][1] + b1;
            float v10 = acc[mi][nj][2] + b0, v11 = acc[mi][nj][3] + b1;
            if (epi == 1) {
                v00 = gelu_exact(v00); v01 = gelu_exact(v01);
                v10 = gelu_exact(v10); v11 = gelu_exact(v11);
                __nv_bfloat16 h, l;
                __nv_bfloat162 hp, lp;
                split_bf16(v00, h, l); hp.x = h; lp.x = l;
                split_bf16(v01, h, l); hp.y = h; lp.y = l;
                *reinterpret_cast<__nv_bfloat162*>(Ch + row0 * N + col) = hp;
                *reinterpret_cast<__nv_bfloat162*>(Cl + row0 * N + col) = lp;
                split_bf16(v10, h, l); hp.x = h; lp.x = l;
                split_bf16(v11, h, l); hp.y = h; lp.y = l;
                *reinterpret_cast<__nv_bfloat162*>(Ch + (row0 + 8) * N + col) = hp;
                *reinterpret_cast<__nv_bfloat162*>(Cl + (row0 + 8) * N + col) = lp;
            } else if (epi == 2) {
                const float2 a0 = *reinterpret_cast<const float2*>(addsrc + row0 * N + col);
                const float2 a1 = *reinterpret_cast<const float2*>(addsrc + (row0 + 8) * N + col);
                *reinterpret_cast<float2*>(Cf + row0 * N + col)       = make_float2(v00 + a0.x, v01 + a0.y);
                *reinterpret_cast<float2*>(Cf + (row0 + 8) * N + col) = make_float2(v10 + a1.x, v11 + a1.y);
            } else {  // epi == 3
                if (bn == 0) {
                    float p00 = fmaxf(v00, __shfl_xor_sync(0xffffffffu, v00, 4));
                    p00 = fmaxf(p00, __shfl_xor_sync(0xffffffffu, p00, 8));
                    float p01 = fmaxf(v01, __shfl_xor_sync(0xffffffffu, v01, 4));
                    p01 = fmaxf(p01, __shfl_xor_sync(0xffffffffu, p01, 8));
                    float p10 = fmaxf(v10, __shfl_xor_sync(0xffffffffu, v10, 4));
                    p10 = fmaxf(p10, __shfl_xor_sync(0xffffffffu, p10, 8));
                    float p11 = fmaxf(v11, __shfl_xor_sync(0xffffffffu, v11, 4));
                    p11 = fmaxf(p11, __shfl_xor_sync(0xffffffffu, p11, 8));
                    if ((lane & 12) == 0) {
                        size_t pr0 = quad_to_prow(row0 >> 2);
                        size_t pr1 = quad_to_prow((row0 + 8) >> 2);
                        *reinterpret_cast<float2*>(Cf + pr0 * 192 + col) = make_float2(p00, p01);
                        *reinterpret_cast<float2*>(Cf + pr1 * 192 + col) = make_float2(p10, p11);
                    }
                } else {
                    size_t qc = col - 192;
                    __nv_bfloat162 p0, p1;
                    p0.x = __float2bfloat16(v00); p0.y = __float2bfloat16(v01);
                    p1.x = __float2bfloat16(v10); p1.y = __float2bfloat16(v11);
                    *reinterpret_cast<__nv_bfloat162*>(Ch + row0 * 576 + qc)       = p0;
                    *reinterpret_cast<__nv_bfloat162*>(Ch + (row0 + 8) * 576 + qc) = p1;
                }
            }
        }
    }
}

// ---------------- LN1 -> bf16 hi/lo, window-major permuted rows -------------
__global__ __launch_bounds__(256) void ln96b_kernel(
    const float* __restrict__ x, const float* __restrict__ g,
    const float* __restrict__ bb,
    __nv_bfloat16* __restrict__ hi, __nv_bfloat16* __restrict__ lo)
{
    int row  = blockIdx.x * 8 + (threadIdx.x >> 5);   // source pixel
    int lane = threadIdx.x & 31;
    const float* p = x + (size_t)row * 96;
    float v0 = p[lane], v1 = p[lane+32], v2 = p[lane+64];
    float s = v0 + v1 + v2;
    #pragma unroll
    for (int o = 16; o > 0; o >>= 1) s += __shfl_xor_sync(0xffffffffu, s, o);
    float mean = s * (1.0f/96.0f);
    float d0 = v0-mean, d1 = v1-mean, d2 = v2-mean;
    float vs = d0*d0 + d1*d1 + d2*d2;
    #pragma unroll
    for (int o = 16; o > 0; o >>= 1) vs += __shfl_xor_sync(0xffffffffu, vs, o);
    float inv = rsqrtf(vs * (1.0f/96.0f) + 1e-6f);
    float y0 = d0*inv*g[lane]    + bb[lane];
    float y1 = d1*inv*g[lane+32] + bb[lane+32];
    float y2 = d2*inv*g[lane+64] + bb[lane+64];
    int wpix = row & 255, hpix = (row >> 8) & 255, b = row >> 16;
    int wi = hpix >> 3, r = hpix & 7, wj = wpix >> 3, c = wpix & 7;
    int t2 = (r >> 1) * 4 + (c >> 1);
    int dq = (r & 1) * 2 + (c & 1);
    size_t wrow = ((((size_t)b * 32 + wi) * 32 + wj) * 16 + t2) * 4 + dq;
    __nv_bfloat16* ph = hi + wrow * 96;
    __nv_bfloat16* pl = lo + wrow * 96;
    __nv_bfloat16 h, l;
    split_bf16(y0, h, l); ph[lane]    = h; pl[lane]    = l;
    split_bf16(y1, h, l); ph[lane+32] = h; pl[lane+32] = l;
    split_bf16(y2, h, l); ph[lane+64] = h; pl[lane+64] = l;
}

__global__ __launch_bounds__(256) void ln192b_kernel(
    const float* __restrict__ x, const float* __restrict__ g,
    const float* __restrict__ bb,
    __nv_bfloat16* __restrict__ hi, __nv_bfloat16* __restrict__ lo)
{
    int row  = blockIdx.x * 8 + (threadIdx.x >> 5);
    int lane = threadIdx.x & 31;
    const float* p = x + (size_t)row * 192;
    float v[6];
    float s = 0.f;
    #pragma unroll
    for (int i = 0; i < 6; i++) { v[i] = p[lane + 32*i]; s += v[i]; }
    #pragma unroll
    for (int o = 16; o > 0; o >>= 1) s += __shfl_xor_sync(0xffffffffu, s, o);
    float mean = s * (1.0f/192.0f);
    float vs = 0.f;
    #pragma unroll
    for (int i = 0; i < 6; i++) { v[i] -= mean; vs += v[i]*v[i]; }
    #pragma unroll
    for (int o = 16; o > 0; o >>= 1) vs += __shfl_xor_sync(0xffffffffu, vs, o);
    float inv = rsqrtf(vs * (1.0f/192.0f) + 1e-6f);
    __nv_bfloat16* ph = hi + (size_t)row * 192;
    __nv_bfloat16* pl = lo + (size_t)row * 192;
    #pragma unroll
    for (int i = 0; i < 6; i++) {
        float y = v[i]*inv*g[lane + 32*i] + bb[lane + 32*i];
        __nv_bfloat16 h, l;
        split_bf16(y, h, l);
        ph[lane + 32*i] = h; pl[lane + 32*i] = l;
    }
}

// ---------------- merged weight conversion + bias concat --------------------
__global__ __launch_bounds__(256) void conv_all_kernel(
    const float* __restrict__ proj_w, const float* __restrict__ qkv_w,
    const float* __restrict__ apw, const float* __restrict__ w1,
    const float* __restrict__ w2,
    const float* __restrict__ proj_b, const float* __restrict__ qkv_b,
    __nv_bfloat16* __restrict__ wfh, __nv_bfloat16* __restrict__ wfl,
    __nv_bfloat16* __restrict__ wah, __nv_bfloat16* __restrict__ wal,
    __nv_bfloat16* __restrict__ w1h, __nv_bfloat16* __restrict__ w1l,
    __nv_bfloat16* __restrict__ w2h, __nv_bfloat16* __restrict__ w2l,
    float* __restrict__ b768)
{
    int i = blockIdx.x * 256 + threadIdx.x;
    const float* W; __nv_bfloat16 *H, *L;
    int K, N, j;
    if (i < 18432)        { W = proj_w; H = wfh;            L = wfl;            K = 96;  N = 192; j = i; }
    else if (i < 73728)   { W = qkv_w;  H = wfh + 18432;    L = wfl + 18432;    K = 96;  N = 576; j = i - 18432; }
    else if (i < 110592)  { W = apw;    H = wah;            L = wal;            K = 192; N = 192; j = i - 73728; }
    else if (i < 258048)  { W = w1;     H = w1h;            L = w1l;            K = 192; N = 768; j = i - 110592; }
    else if (i < 405504)  { W = w2;     H = w2h;            L = w2l;            K = 768; N = 192; j = i - 258048; }
    else if (i < 406272)  { j = i - 405504; b768[j] = (j < 192) ? proj_b[j] : qkv_b[j - 192]; return; }
    else return;
    int n = j / K, k = j % K;
    float v = W[(size_t)k * N + n];
    __nv_bfloat16 h, l;
    split_bf16(v, h, l);
    H[j] = h; L[j] = l;
}

// ---------------- windowed attention: packed bf16x2, 4x4 reg blocking -------
#define ATT_SMEM 70912

__global__ __launch_bounds__(256, 2) void attn_kernel(
    const __nv_bfloat16* __restrict__ qkv,
    __nv_bfloat16* __restrict__ Oh, __nv_bfloat16* __restrict__ Ol)
{
    extern __shared__ float sm[];
    uint32_t* qp = reinterpret_cast<uint32_t*>(sm);                    // [16][100]
    uint32_t* kh = qp + 1600;                                          // [3][64][35]
    __nv_bfloat16* vh = reinterpret_cast<__nv_bfloat16*>(kh + 6720);   // [3][64][66]
    float* sc = sm + 14656;                                            // [3][16][64]

    int w = blockIdx.x;
    int b = w >> 10, wi = (w >> 5) & 31, wj = w & 31;
    int tid = threadIdx.x;
    const uint32_t* qk = reinterpret_cast<const uint32_t*>(qkv + (size_t)w * 64 * 576);

    // 1) pooled q (bf16-exact max), packed bf16x2
    for (int i = tid; i < 16*96; i += 256) {
        int t2 = i / 96, c2 = i % 96;
        float m0 = -1e30f, m1 = -1e30f;
        #pragma unroll
        for (int dq = 0; dq < 4; dq++) {
            uint32_t wd = qk[(t2*4 + dq)*288 + c2];
            __nv_bfloat162 v = *reinterpret_cast<__nv_bfloat162*>(&wd);
            m0 = fmaxf(m0, __bfloat162float(v.x));
            m1 = fmaxf(m1, __bfloat162float(v.y));
        }
        __nv_bfloat162 r;
        r.x = __float2bfloat16(m0); r.y = __float2bfloat16(m1);
        qp[t2*100 + c2] = *reinterpret_cast<uint32_t*>(&r);
    }
    // 2) k packed rows; v transposed to [d][s] bf16
    for (int i = tid; i < 3*64*32; i += 256) {
        int d2 = i & 31, s = (i >> 5) & 63, h = i >> 11;
        kh[(h*64 + s)*35 + d2] = qk[s*288 + 96 + h*32 + d2];
        uint32_t vw = qk[s*288 + 192 + h*32 + d2];
        __nv_bfloat162 vv = *reinterpret_cast<__nv_bfloat162*>(&vw);
        vh[(h*64 + d2*2    )*66 + s] = vv.x;
        vh[(h*64 + d2*2 + 1)*66 + s] = vv.y;
    }
    __syncthreads();

    // 3) scores: 192 threads, 4 t2-rows x 4 keys each
    if (tid < 192) {
        int sg = tid & 15, tg = (tid >> 4) & 3, h = tid >> 6;
        float acc[4][4] = {};
        #pragma unroll 4
        for (int d2 = 0; d2 < 32; d2++) {
            float2 qv[4], kv[4];
            #pragma unroll
            for (int i = 0; i < 4; i++) {
                uint32_t qw = qp[(tg*4 + i)*100 + h*32 + d2];
                qv[i] = __bfloat1622float2(*reinterpret_cast<__nv_bfloat162*>(&qw));
                uint32_t kw = kh[(h*64 + sg*4 + i)*35 + d2];
                kv[i] = __bfloat1622float2(*reinterpret_cast<__nv_bfloat162*>(&kw));
            }
            #pragma unroll
            for (int i = 0; i < 4; i++)
                #pragma unroll
                for (int j = 0; j < 4; j++) {
                    acc[i][j] = fmaf(qv[i].x, kv[j].x, acc[i][j]);
                    acc[i][j] = fmaf(qv[i].y, kv[j].y, acc[i][j]);
                }
        }
        #pragma unroll
        for (int i = 0; i < 4; i++)
            #pragma unroll
            for (int j = 0; j < 4; j++)
                sc[(h*16 + tg*4 + i)*64 + sg*4 + j] = acc[i][j] * 0.125f;
    }
    __syncthreads();

    // 4) softmax: 48 rows over 8 warps
    {
        int warp = tid >> 5, lane = tid & 31;
        for (int r = warp; r < 48; r += 8) {
            float v0 = sc[r*64 + lane], v1 = sc[r*64 + 32 + lane];
            float mx = fmaxf(v0, v1);
            #pragma unroll
            for (int o = 16; o > 0; o >>= 1)
                mx = fmaxf(mx, __shfl_xor_sync(0xffffffffu, mx, o));
            float e0 = expf(v0 - mx), e1 = expf(v1 - mx);
            float ss = e0 + e1;
            #pragma unroll
            for (int o = 16; o > 0; o >>= 1)
                ss += __shfl_xor_sync(0xffffffffu, ss, o);
            float inv = 1.f / ss;
            sc[r*64 + lane]      = e0 * inv;
            sc[r*64 + 32 + lane] = e1 * inv;
        }
    }
    __syncthreads();

    // 5) out: 192 threads, 4 t2-rows x 4 dims each
    if (tid < 192) {
        int dg = tid & 15, tg = (tid >> 4) & 3, h = tid >> 6;
        float acc[4][4] = {};
        const uint32_t* vhw = reinterpret_cast<const uint32_t*>(vh);
        #pragma unroll 4
        for (int s2 = 0; s2 < 32; s2++) {
            float2 pv[4], vv[4];
            #pragma unroll
            for (int i = 0; i < 4; i++) {
                pv[i] = *reinterpret_cast<const float2*>(&sc[(h*16 + tg*4 + i)*64 + s2*2]);
                uint32_t vw = vhw[(h*64 + dg*4 + i)*33 + s2];
                vv[i] = __bfloat1622float2(*reinterpret_cast<__nv_bfloat162*>(&vw));
            }
            #pragma unroll
            for (int i = 0; i < 4; i++)
                #pragma unroll
                for (int j = 0; j < 4; j++) {
                    acc[i][j] = fmaf(pv[i].x, vv[j].x, acc[i][j]);
                    acc[i][j] = fmaf(pv[i].y, vv[j].y, acc[i][j]);
                }
        }
        #pragma unroll
        for (int i = 0; i < 4; i++) {
            int t2 = tg*4 + i;
            size_t orow = ((size_t)(b*128 + wi*4 + (t2 >> 2)))*128 + wj*4 + (t2 & 3);
            size_t off = orow*192 + h*64 + dg*4;
            #pragma unroll
            for (int j = 0; j < 4; j += 2) {
                __nv_bfloat16 h0, l0, h1, l1;
                split_bf16(acc[i][j],   h0, l0);
                split_bf16(acc[i][j+1], h1, l1);
                __nv_bfloat162 hp, lp;
                hp.x = h0; hp.y = h1;
                lp.x = l0; lp.y = l1;
                *reinterpret_cast<__nv_bfloat162*>(Oh + off + j) = hp;
                *reinterpret_cast<__nv_bfloat162*>(Ol + off + j) = lp;
            }
        }
    }
}

// ---------------- launch ----------------------------------------------------
extern "C" void kernel_launch(void* const* d_in, const int* in_sizes, int n_in,
                              void* d_out, int out_size)
{
    const float* x       = (const float*)d_in[0];
    const float* n1g     = (const float*)d_in[1];
    const float* n1b     = (const float*)d_in[2];
    const float* proj_w  = (const float*)d_in[3];
    const float* proj_b  = (const float*)d_in[4];
    const float* qkv_w   = (const float*)d_in[5];
    const float* qkv_b   = (const float*)d_in[6];
    const float* apw     = (const float*)d_in[7];
    const float* apb     = (const float*)d_in[8];
    const float* n2g     = (const float*)d_in[9];
    const float* n2b     = (const float*)d_in[10];
    const float* w1      = (const float*)d_in[11];
    const float* b1      = (const float*)d_in[12];
    const float* w2      = (const float*)d_in[13];
    const float* b2      = (const float*)d_in[14];
    float* y = (float*)d_out;

    __nv_bfloat16 *xh, *xl, *qkvb, *oh, *ol, *ynh, *ynl, *hh, *hl;
    __nv_bfloat16 *wfh, *wfl, *wah, *wal, *w1h, *w1l, *w2h, *w2l;
    float *b768;
    cudaGetSymbolAddress((void**)&xh,  g_xh);
    cudaGetSymbolAddress((void**)&xl,  g_xl);
    cudaGetSymbolAddress((void**)&qkvb, g_qkvb);
    cudaGetSymbolAddress((void**)&oh,  g_oh);
    cudaGetSymbolAddress((void**)&ol,  g_ol);
    cudaGetSymbolAddress((void**)&ynh, g_ynh);
    cudaGetSymbolAddress((void**)&ynl, g_ynl);
    cudaGetSymbolAddress((void**)&hh,  g_hh);
    cudaGetSymbolAddress((void**)&hl,  g_hl);
    cudaGetSymbolAddress((void**)&wfh, g_wfh);
    cudaGetSymbolAddress((void**)&wfl, g_wfl);
    cudaGetSymbolAddress((void**)&wah, g_wah);
    cudaGetSymbolAddress((void**)&wal, g_wal);
    cudaGetSymbolAddress((void**)&w1h, g_w1h);
    cudaGetSymbolAddress((void**)&w1l, g_w1l);
    cudaGetSymbolAddress((void**)&w2h, g_w2h);
    cudaGetSymbolAddress((void**)&w2l, g_w2l);
    cudaGetSymbolAddress((void**)&b768, g_b768);

    static bool attr_done = false;
    if (!attr_done) {
        cudaFuncSetAttribute(attn_kernel,
            cudaFuncAttributeMaxDynamicSharedMemorySize, ATT_SMEM);
        cudaFuncSetAttribute(gemm_mma,
            cudaFuncAttributeMaxDynamicSharedMemorySize, GEMM_SMEM);
        attr_done = true;
    }

    // 0) merged weight conversions + bias concat
    conv_all_kernel<<<(406272 + 255) / 256, 256>>>(
        proj_w, qkv_w, apw, w1, w2, proj_b, qkv_b,
        wfh, wfl, wah, wal, w1h, w1l, w2h, w2l, b768);
    // 1) LN1 -> bf16 hi/lo (window-major rows)
    ln96b_kernel<<<NPIX/8, 256>>>(x, n1g, n1b, xh, xl);
    // 2) fused proj+qkv GEMM: tile0 (x3) -> pooled y, tiles1-3 (x1) -> qkv bf16
    gemm_mma<<<dim3(4, NPIX/128), 256, GEMM_SMEM>>>(
        xh, xl, wfh, wfl, 96, 768, 3, b768, y, qkvb, nullptr, nullptr);
    // 3) windowed attention -> O (bf16 hi/lo)
    attn_kernel<<<NWIN, 256, ATT_SMEM>>>(qkvb, oh, ol);
    // 4) attn-proj GEMM: y += O @ apw + apb
    gemm_mma<<<dim3(1, NPOOL/128), 256, GEMM_SMEM>>>(
        oh, ol, wah, wal, 192, 192, 2, apb, y, nullptr, nullptr, y);
    // 5) LN2 -> bf16 hi/lo
    ln192b_kernel<<<NPOOL/8, 256>>>(y, n2g, n2b, ynh, ynl);
    // 6) mlp1 GEMM + gelu -> h (bf16 hi/lo)
    gemm_mma<<<dim3(4, NPOOL/128), 256, GEMM_SMEM>>>(
        ynh, ynl, w1h, w1l, 192, 768, 1, b1, nullptr, hh, hl, nullptr);
    // 7) mlp2 GEMM + residual add -> y (d_out)
    gemm_mma<<<dim3(1, NPOOL/128), 256, GEMM_SMEM>>>(
        hh, hl, w2h, w2l, 768, 192, 2, b2, y, nullptr, nullptr, y);
}

// round 11
// speedup vs baseline: 1.2931x; 1.2931x over previous
#include <cuda_runtime.h>
#include <cuda_bf16.h>
#include <cuda_fp16.h>
#include <cstdint>
#include <math.h>

// ===========================================================================
// MultiScaleBlock (sm_103 PTX, HMMA mma.sync path).
// Window-major pixel permutation. Fused proj+qkv GEMM (bf16 x3 proj tile /
// x1 qkv tiles, maxpool in epilogue, DRAM-bound) + fp16 x1 GEMMs for
// attn-proj / mlp1 / mlp2 (MMA-bound: 3x fewer HMMA than bf16 x3).
// Attention: bf16x2-packed smem + 4x4 register blocking -> fp16 O.
// ===========================================================================

#define NPIX   (4*256*256)     // 262144
#define NPOOL  (4*128*128)     // 65536
#define NWIN   (4*32*32)       // 4096

// ---------------- scratch (device globals) ----------------------------------
__device__ __nv_bfloat16 g_xh [(size_t)NPIX  * 96];
__device__ __nv_bfloat16 g_xl [(size_t)NPIX  * 96];
__device__ __nv_bfloat16 g_qkvb[(size_t)NPIX * 576];     // bf16 qkv, window-major
__device__ __half        g_o  [(size_t)NPOOL * 192];     // attention O (fp16)
__device__ __half        g_yn [(size_t)NPOOL * 192];     // LN2 out (fp16)
__device__ __half        g_h  [(size_t)NPOOL * 768];     // mlp hidden (fp16)
// weights: fused proj+qkv [N][K] bf16 hi/lo; others fp16 [N][K]
__device__ __nv_bfloat16 g_wfh[768*96],  g_wfl[768*96];
__device__ __half        g_wa16[192*192];
__device__ __half        g_w116[768*192];
__device__ __half        g_w216[192*768];
__device__ float         g_b768[768];

// ---------------- helpers ---------------------------------------------------
__device__ __forceinline__ uint32_t smem_u32(const void* p) {
    uint32_t a;
    asm("{ .reg .u64 t; cvta.to.shared.u64 t, %1; cvt.u32.u64 %0, t; }"
        : "=r"(a) : "l"(p));
    return a;
}
__device__ __forceinline__ void cp16(uint32_t s, const void* g) {
    asm volatile("cp.async.ca.shared.global [%0], [%1], 16;"
                 :: "r"(s), "l"(g) : "memory");
}
__device__ __forceinline__ void cp_commit() {
    asm volatile("cp.async.commit_group;" ::: "memory");
}
template<int N>
__device__ __forceinline__ void cp_wait() {
    asm volatile("cp.async.wait_group %0;" :: "n"(N) : "memory");
}
__device__ __forceinline__ void ldsm4(uint32_t* r, uint32_t a) {
    asm volatile("ldmatrix.sync.aligned.m8n8.x4.shared.b16 {%0,%1,%2,%3}, [%4];"
        : "=r"(r[0]), "=r"(r[1]), "=r"(r[2]), "=r"(r[3]) : "r"(a));
}
__device__ __forceinline__ void mma_bf16(float* d, const uint32_t* a,
                                         uint32_t b0, uint32_t b1) {
    asm volatile(
        "mma.sync.aligned.m16n8k16.row.col.f32.bf16.bf16.f32 "
        "{%0,%1,%2,%3}, {%4,%5,%6,%7}, {%8,%9}, {%0,%1,%2,%3};"
        : "+f"(d[0]), "+f"(d[1]), "+f"(d[2]), "+f"(d[3])
        : "r"(a[0]), "r"(a[1]), "r"(a[2]), "r"(a[3]), "r"(b0), "r"(b1));
}
__device__ __forceinline__ void mma_fp16(float* d, const uint32_t* a,
                                         uint32_t b0, uint32_t b1) {
    asm volatile(
        "mma.sync.aligned.m16n8k16.row.col.f32.f16.f16.f32 "
        "{%0,%1,%2,%3}, {%4,%5,%6,%7}, {%8,%9}, {%0,%1,%2,%3};"
        : "+f"(d[0]), "+f"(d[1]), "+f"(d[2]), "+f"(d[3])
        : "r"(a[0]), "r"(a[1]), "r"(a[2]), "r"(a[3]), "r"(b0), "r"(b1));
}
__device__ __forceinline__ void split_bf16(float v, __nv_bfloat16& h, __nv_bfloat16& l) {
    h = __float2bfloat16(v);
    l = __float2bfloat16(v - __bfloat162float(h));
}
__device__ __forceinline__ float gelu_exact(float v) {
    return 0.5f * v * (1.0f + erff(v * 0.70710678118654752f));
}
// window-major quad index -> standard pooled row
__device__ __forceinline__ size_t quad_to_prow(size_t g) {
    int t2 = (int)(g & 15);
    int wj = (int)((g >> 4) & 31);
    int wi = (int)((g >> 9) & 31);
    int b  = (int)(g >> 14);
    return ((size_t)(b * 128 + wi * 4 + (t2 >> 2))) * 128 + wj * 4 + (t2 & 3);
}

// ======== fused proj+qkv GEMM (bf16), BM=128 BN=192 BK=32, 3-stage, 1 CTA/SM
// tile0 (bn==0): x3 hi/lo -> pooled y (fp32); tiles 1-3: x1 -> qkv bf16.
#define LDA     40                         // BK + 8 (half-words)
#define SA_HI   0
#define SA_LO   (128*LDA*2)                // 10240
#define SB_HI   (2*128*LDA*2)              // 20480
#define SB_LO   (SB_HI + 192*LDA*2)        // 35840
#define STAGE_B (SB_LO + 192*LDA*2)        // 51200
#define GEMM_SMEM (3*STAGE_B)              // 153600

__global__ __launch_bounds__(256, 1) void gemm_fused(
    const __nv_bfloat16* __restrict__ Ah, const __nv_bfloat16* __restrict__ Al,
    const __nv_bfloat16* __restrict__ Bh, const __nv_bfloat16* __restrict__ Bl,
    const float* __restrict__ bias,
    float* __restrict__ Cf, __nv_bfloat16* __restrict__ Ch)
{
    extern __shared__ char smem[];
    const uint32_t sb = smem_u32(smem);
    const int tid = threadIdx.x, lane = tid & 31, warp = tid >> 5;
    const int wm = (warp >> 1) * 32;
    const int wn = (warp & 1) * 96;
    const int K = 96;
    const size_t bm = (size_t)blockIdx.y * 128;
    const size_t bn = (size_t)blockIdx.x * 192;
    const int C = 3;
    const bool x3 = (blockIdx.x == 0);

    const __nv_bfloat16* AhB = Ah + bm * K;
    const __nv_bfloat16* AlB = Al + bm * K;
    const __nv_bfloat16* BhB = Bh + bn * K;
    const __nv_bfloat16* BlB = Bl + bn * K;

    float acc[2][12][4];
    #pragma unroll
    for (int i = 0; i < 2; i++)
        #pragma unroll
        for (int j = 0; j < 12; j++)
            #pragma unroll
            for (int q = 0; q < 4; q++) acc[i][j][q] = 0.f;

    auto load_stage = [&](int s, int c) {
        const uint32_t st = sb + (uint32_t)s * STAGE_B;
        const size_t k0 = (size_t)c * 32;
        #pragma unroll
        for (int i = tid; i < 512; i += 256) {
            int r = i >> 2, q = i & 3;
            uint32_t d = st + (uint32_t)(r * LDA + q * 8) * 2;
            size_t go = (size_t)r * K + k0 + q * 8;
            cp16(d + SA_HI, AhB + go);
            if (x3) cp16(d + SA_LO, AlB + go);
        }
        #pragma unroll
        for (int i = tid; i < 768; i += 256) {
            int r = i >> 2, q = i & 3;
            uint32_t d = st + (uint32_t)(r * LDA + q * 8) * 2;
            size_t go = (size_t)r * K + k0 + q * 8;
            cp16(d + SB_HI, BhB + go);
            if (x3) cp16(d + SB_LO, BlB + go);
        }
        cp_commit();
    };

    auto compute_stage = [&](int s) {
        const uint32_t st = sb + (uint32_t)s * STAGE_B;
        #pragma unroll
        for (int k16 = 0; k16 < 2; k16++) {
            uint32_t ah[2][4], al[2][4];
            #pragma unroll
            for (int mi = 0; mi < 2; mi++) {
                int row = wm + mi * 16 + (lane & 15);
                int col = k16 * 16 + (lane >> 4) * 8;
                uint32_t ad = st + (uint32_t)(row * LDA + col) * 2;
                ldsm4(ah[mi], ad + SA_HI);
                if (x3) ldsm4(al[mi], ad + SA_LO);
            }
            #pragma unroll
            for (int ng = 0; ng < 6; ng++) {
                uint32_t bh[4], bl[4];
                int nr = wn + ng * 16 + (lane & 7) + ((lane >> 4) & 1) * 8;
                int bc = k16 * 16 + ((lane >> 3) & 1) * 8;
                uint32_t bd = st + (uint32_t)(nr * LDA + bc) * 2;
                ldsm4(bh, bd + SB_HI);
                if (x3) ldsm4(bl, bd + SB_LO);
                #pragma unroll
                for (int mi = 0; mi < 2; mi++) {
                    #pragma unroll
                    for (int sub = 0; sub < 2; sub++) {
                        float* d = acc[mi][ng * 2 + sub];
                        mma_bf16(d, ah[mi], bh[2*sub], bh[2*sub+1]);
                        if (x3) {
                            mma_bf16(d, ah[mi], bl[2*sub], bl[2*sub+1]);
                            mma_bf16(d, al[mi], bh[2*sub], bh[2*sub+1]);
                        }
                    }
                }
            }
        }
    };

    load_stage(0, 0);
    load_stage(1, 1);
    for (int c = 0; c < C; c++) {
        if (c + 1 < C) { cp_wait<1>(); } else { cp_wait<0>(); }
        __syncthreads();
        if (c + 2 < C) load_stage((c + 2) % 3, c + 2);
        compute_stage(c % 3);
        __syncthreads();
    }

    // ---- epilogue: tile0 -> fused 2x2 maxpool into y; tiles1-3 -> qkv bf16 -
    #pragma unroll
    for (int mi = 0; mi < 2; mi++) {
        #pragma unroll
        for (int nj = 0; nj < 12; nj++) {
            size_t row0 = bm + wm + mi * 16 + (lane >> 2);
            size_t col  = bn + wn + nj * 8 + 2 * (lane & 3);
            float b0 = bias[col], b1 = bias[col + 1];
            float v00 = acc[mi][nj][0] + b0, v01 = acc[mi][nj][1] + b1;
            float v10 = acc[mi][nj][2] + b0, v11 = acc[mi][nj][3] + b1;
            if (bn == 0) {
                float p00 = fmaxf(v00, __shfl_xor_sync(0xffffffffu, v00, 4));
                p00 = fmaxf(p00, __shfl_xor_sync(0xffffffffu, p00, 8));
                float p01 = fmaxf(v01, __shfl_xor_sync(0xffffffffu, v01, 4));
                p01 = fmaxf(p01, __shfl_xor_sync(0xffffffffu, p01, 8));
                float p10 = fmaxf(v10, __shfl_xor_sync(0xffffffffu, v10, 4));
                p10 = fmaxf(p10, __shfl_xor_sync(0xffffffffu, p10, 8));
                float p11 = fmaxf(v11, __shfl_xor_sync(0xffffffffu, v11, 4));
                p11 = fmaxf(p11, __shfl_xor_sync(0xffffffffu, p11, 8));
                if ((lane & 12) == 0) {
                    size_t pr0 = quad_to_prow(row0 >> 2);
                    size_t pr1 = quad_to_prow((row0 + 8) >> 2);
                    *reinterpret_cast<float2*>(Cf + pr0 * 192 + col) = make_float2(p00, p01);
                    *reinterpret_cast<float2*>(Cf + pr1 * 192 + col) = make_float2(p10, p11);
                }
            } else {
                size_t qc = col - 192;
                __nv_bfloat162 p0, p1;
                p0.x = __float2bfloat16(v00); p0.y = __float2bfloat16(v01);
                p1.x = __float2bfloat16(v10); p1.y = __float2bfloat16(v11);
                *reinterpret_cast<__nv_bfloat162*>(Ch + row0 * 576 + qc)       = p0;
                *reinterpret_cast<__nv_bfloat162*>(Ch + (row0 + 8) * 576 + qc) = p1;
            }
        }
    }
}

// ======== fp16 x1 GEMM, BM=128 BN=192 BK=32, 3-stage, 2 CTA/SM ==============
// epi: 1 = gelu -> fp16; 2 = +bias +addsrc -> fp32
#define LDAH     40
#define SAH      0
#define SBH      (128*LDAH*2)               // 10240
#define STAGEH   (SBH + 192*LDAH*2)         // 25600
#define GEMMH_SMEM (3*STAGEH)               // 76800

__global__ __launch_bounds__(256, 2) void gemm_f16(
    const __half* __restrict__ A, const __half* __restrict__ B,
    int K, int N, int epi,
    const float* __restrict__ bias,
    float* __restrict__ Cf, __half* __restrict__ Ch,
    const float* __restrict__ addsrc)
{
    extern __shared__ char smem[];
    const uint32_t sb = smem_u32(smem);
    const int tid = threadIdx.x, lane = tid & 31, warp = tid >> 5;
    const int wm = (warp >> 1) * 32;
    const int wn = (warp & 1) * 96;
    const size_t bm = (size_t)blockIdx.y * 128;
    const size_t bn = (size_t)blockIdx.x * 192;
    const int C = K >> 5;

    const __half* AB = A + bm * K;
    const __half* BB = B + bn * K;

    float acc[2][12][4];
    #pragma unroll
    for (int i = 0; i < 2; i++)
        #pragma unroll
        for (int j = 0; j < 12; j++)
            #pragma unroll
            for (int q = 0; q < 4; q++) acc[i][j][q] = 0.f;

    auto load_stage = [&](int s, int c) {
        const uint32_t st = sb + (uint32_t)s * STAGEH;
        const size_t k0 = (size_t)c * 32;
        #pragma unroll
        for (int i = tid; i < 512; i += 256) {
            int r = i >> 2, q = i & 3;
            cp16(st + SAH + (uint32_t)(r * LDAH + q * 8) * 2,
                 AB + (size_t)r * K + k0 + q * 8);
        }
        #pragma unroll
        for (int i = tid; i < 768; i += 256) {
            int r = i >> 2, q = i & 3;
            cp16(st + SBH + (uint32_t)(r * LDAH + q * 8) * 2,
                 BB + (size_t)r * K + k0 + q * 8);
        }
        cp_commit();
    };

    auto compute_stage = [&](int s) {
        const uint32_t st = sb + (uint32_t)s * STAGEH;
        #pragma unroll
        for (int k16 = 0; k16 < 2; k16++) {
            uint32_t ah[2][4];
            #pragma unroll
            for (int mi = 0; mi < 2; mi++) {
                int row = wm + mi * 16 + (lane & 15);
                int col = k16 * 16 + (lane >> 4) * 8;
                ldsm4(ah[mi], st + SAH + (uint32_t)(row * LDAH + col) * 2);
            }
            #pragma unroll
            for (int ng = 0; ng < 6; ng++) {
                uint32_t bh[4];
                int nr = wn + ng * 16 + (lane & 7) + ((lane >> 4) & 1) * 8;
                int bc = k16 * 16 + ((lane >> 3) & 1) * 8;
                ldsm4(bh, st + SBH + (uint32_t)(nr * LDAH + bc) * 2);
                #pragma unroll
                for (int mi = 0; mi < 2; mi++) {
                    #pragma unroll
                    for (int sub = 0; sub < 2; sub++)
                        mma_fp16(acc[mi][ng * 2 + sub], ah[mi], bh[2*sub], bh[2*sub+1]);
                }
            }
        }
    };

    load_stage(0, 0);
    load_stage(1, 1);
    for (int c = 0; c < C; c++) {
        if (c + 1 < C) { cp_wait<1>(); } else { cp_wait<0>(); }
        __syncthreads();
        if (c + 2 < C) load_stage((c + 2) % 3, c + 2);
        compute_stage(c % 3);
        __syncthreads();
    }

    #pragma unroll
    for (int mi = 0; mi < 2; mi++) {
        #pragma unroll
        for (int nj = 0; nj < 12; nj++) {
            size_t row0 = bm + wm + mi * 16 + (lane >> 2);
            size_t col  = bn + wn + nj * 8 + 2 * (lane & 3);
            float b0 = bias[col], b1 = bias[col + 1];
            float v00 = acc[mi][nj][0] + b0, v01 = acc[mi][nj][1] + b1;
            float v10 = acc[mi][nj][2] + b0, v11 = acc[mi][nj][3] + b1;
            if (epi == 1) {
                v00 = gelu_exact(v00); v01 = gelu_exact(v01);
                v10 = gelu_exact(v10); v11 = gelu_exact(v11);
                *reinterpret_cast<__half2*>(Ch + row0 * N + col)       = __floats2half2_rn(v00, v01);
                *reinterpret_cast<__half2*>(Ch + (row0 + 8) * N + col) = __floats2half2_rn(v10, v11);
            } else {
                const float2 a0 = *reinterpret_cast<const float2*>(addsrc + row0 * N + col);
                const float2 a1 = *reinterpret_cast<const float2*>(addsrc + (row0 + 8) * N + col);
                *reinterpret_cast<float2*>(Cf + row0 * N + col)       = make_float2(v00 + a0.x, v01 + a0.y);
                *reinterpret_cast<float2*>(Cf + (row0 + 8) * N + col) = make_float2(v10 + a1.x, v11 + a1.y);
            }
        }
    }
}

// ---------------- LN1 -> bf16 hi/lo, window-major permuted rows -------------
__global__ __launch_bounds__(256) void ln96b_kernel(
    const float* __restrict__ x, const float* __restrict__ g,
    const float* __restrict__ bb,
    __nv_bfloat16* __restrict__ hi, __nv_bfloat16* __restrict__ lo)
{
    int row  = blockIdx.x * 8 + (threadIdx.x >> 5);
    int lane = threadIdx.x & 31;
    const float* p = x + (size_t)row * 96;
    float v0 = p[lane], v1 = p[lane+32], v2 = p[lane+64];
    float s = v0 + v1 + v2;
    #pragma unroll
    for (int o = 16; o > 0; o >>= 1) s += __shfl_xor_sync(0xffffffffu, s, o);
    float mean = s * (1.0f/96.0f);
    float d0 = v0-mean, d1 = v1-mean, d2 = v2-mean;
    float vs = d0*d0 + d1*d1 + d2*d2;
    #pragma unroll
    for (int o = 16; o > 0; o >>= 1) vs += __shfl_xor_sync(0xffffffffu, vs, o);
    float inv = rsqrtf(vs * (1.0f/96.0f) + 1e-6f);
    float y0 = d0*inv*g[lane]    + bb[lane];
    float y1 = d1*inv*g[lane+32] + bb[lane+32];
    float y2 = d2*inv*g[lane+64] + bb[lane+64];
    int wpix = row & 255, hpix = (row >> 8) & 255, b = row >> 16;
    int wi = hpix >> 3, r = hpix & 7, wj = wpix >> 3, c = wpix & 7;
    int t2 = (r >> 1) * 4 + (c >> 1);
    int dq = (r & 1) * 2 + (c & 1);
    size_t wrow = ((((size_t)b * 32 + wi) * 32 + wj) * 16 + t2) * 4 + dq;
    __nv_bfloat16* ph = hi + wrow * 96;
    __nv_bfloat16* pl = lo + wrow * 96;
    __nv_bfloat16 h, l;
    split_bf16(y0, h, l); ph[lane]    = h; pl[lane]    = l;
    split_bf16(y1, h, l); ph[lane+32] = h; pl[lane+32] = l;
    split_bf16(y2, h, l); ph[lane+64] = h; pl[lane+64] = l;
}

// ---------------- LN2 -> fp16 -----------------------------------------------
__global__ __launch_bounds__(256) void ln192h_kernel(
    const float* __restrict__ x, const float* __restrict__ g,
    const float* __restrict__ bb, __half* __restrict__ out)
{
    int row  = blockIdx.x * 8 + (threadIdx.x >> 5);
    int lane = threadIdx.x & 31;
    const float* p = x + (size_t)row * 192;
    float v[6];
    float s = 0.f;
    #pragma unroll
    for (int i = 0; i < 6; i++) { v[i] = p[lane + 32*i]; s += v[i]; }
    #pragma unroll
    for (int o = 16; o > 0; o >>= 1) s += __shfl_xor_sync(0xffffffffu, s, o);
    float mean = s * (1.0f/192.0f);
    float vs = 0.f;
    #pragma unroll
    for (int i = 0; i < 6; i++) { v[i] -= mean; vs += v[i]*v[i]; }
    #pragma unroll
    for (int o = 16; o > 0; o >>= 1) vs += __shfl_xor_sync(0xffffffffu, vs, o);
    float inv = rsqrtf(vs * (1.0f/192.0f) + 1e-6f);
    __half* q = out + (size_t)row * 192;
    #pragma unroll
    for (int i = 0; i < 6; i++)
        q[lane + 32*i] = __float2half(v[i]*inv*g[lane + 32*i] + bb[lane + 32*i]);
}

// ---------------- merged weight conversion + bias concat --------------------
__global__ __launch_bounds__(256) void conv_all_kernel(
    const float* __restrict__ proj_w, const float* __restrict__ qkv_w,
    const float* __restrict__ apw, const float* __restrict__ w1,
    const float* __restrict__ w2,
    const float* __restrict__ proj_b, const float* __restrict__ qkv_b,
    __nv_bfloat16* __restrict__ wfh, __nv_bfloat16* __restrict__ wfl,
    __half* __restrict__ wa16, __half* __restrict__ w116,
    __half* __restrict__ w216, float* __restrict__ b768)
{
    int i = blockIdx.x * 256 + threadIdx.x;
    if (i < 73728) {
        // fused proj+qkv: bf16 hi/lo
        const float* W; int K = 96, N, j;
        __nv_bfloat16 *H, *L;
        if (i < 18432) { W = proj_w; N = 192; j = i;        H = wfh;         L = wfl; }
        else           { W = qkv_w;  N = 576; j = i - 18432; H = wfh + 18432; L = wfl + 18432; }
        int n = j / K, k = j % K;
        float v = W[(size_t)k * N + n];
        __nv_bfloat16 h, l;
        split_bf16(v, h, l);
        H[j] = h; L[j] = l;
    } else if (i < 405504) {
        const float* W; __half* H; int K, N, j;
        if (i < 110592)      { W = apw; H = wa16; K = 192; N = 192; j = i - 73728; }
        else if (i < 258048) { W = w1;  H = w116; K = 192; N = 768; j = i - 110592; }
        else                 { W = w2;  H = w216; K = 768; N = 192; j = i - 258048; }
        int n = j / K, k = j % K;
        H[j] = __float2half(W[(size_t)k * N + n]);
    } else if (i < 406272) {
        int j = i - 405504;
        b768[j] = (j < 192) ? proj_b[j] : qkv_b[j - 192];
    }
}

// ---------------- windowed attention: packed bf16x2, 4x4 reg blocking -------
#define ATT_SMEM 70912

__global__ __launch_bounds__(256, 2) void attn_kernel(
    const __nv_bfloat16* __restrict__ qkv, __half* __restrict__ O)
{
    extern __shared__ float sm[];
    uint32_t* qp = reinterpret_cast<uint32_t*>(sm);                    // [16][100]
    uint32_t* kh = qp + 1600;                                          // [3][64][35]
    __nv_bfloat16* vh = reinterpret_cast<__nv_bfloat16*>(kh + 6720);   // [3][64][66]
    float* sc = sm + 14656;                                            // [3][16][64]

    int w = blockIdx.x;
    int b = w >> 10, wi = (w >> 5) & 31, wj = w & 31;
    int tid = threadIdx.x;
    const uint32_t* qk = reinterpret_cast<const uint32_t*>(qkv + (size_t)w * 64 * 576);

    for (int i = tid; i < 16*96; i += 256) {
        int t2 = i / 96, c2 = i % 96;
        float m0 = -1e30f, m1 = -1e30f;
        #pragma unroll
        for (int dq = 0; dq < 4; dq++) {
            uint32_t wd = qk[(t2*4 + dq)*288 + c2];
            __nv_bfloat162 v = *reinterpret_cast<__nv_bfloat162*>(&wd);
            m0 = fmaxf(m0, __bfloat162float(v.x));
            m1 = fmaxf(m1, __bfloat162float(v.y));
        }
        __nv_bfloat162 r;
        r.x = __float2bfloat16(m0); r.y = __float2bfloat16(m1);
        qp[t2*100 + c2] = *reinterpret_cast<uint32_t*>(&r);
    }
    for (int i = tid; i < 3*64*32; i += 256) {
        int d2 = i & 31, s = (i >> 5) & 63, h = i >> 11;
        kh[(h*64 + s)*35 + d2] = qk[s*288 + 96 + h*32 + d2];
        uint32_t vw = qk[s*288 + 192 + h*32 + d2];
        __nv_bfloat162 vv = *reinterpret_cast<__nv_bfloat162*>(&vw);
        vh[(h*64 + d2*2    )*66 + s] = vv.x;
        vh[(h*64 + d2*2 + 1)*66 + s] = vv.y;
    }
    __syncthreads();

    if (tid < 192) {
        int sg = tid & 15, tg = (tid >> 4) & 3, h = tid >> 6;
        float acc[4][4] = {};
        #pragma unroll 4
        for (int d2 = 0; d2 < 32; d2++) {
            float2 qv[4], kv[4];
            #pragma unroll
            for (int i = 0; i < 4; i++) {
                uint32_t qw = qp[(tg*4 + i)*100 + h*32 + d2];
                qv[i] = __bfloat1622float2(*reinterpret_cast<__nv_bfloat162*>(&qw));
                uint32_t kw = kh[(h*64 + sg*4 + i)*35 + d2];
                kv[i] = __bfloat1622float2(*reinterpret_cast<__nv_bfloat162*>(&kw));
            }
            #pragma unroll
            for (int i = 0; i < 4; i++)
                #pragma unroll
                for (int j = 0; j < 4; j++) {
                    acc[i][j] = fmaf(qv[i].x, kv[j].x, acc[i][j]);
                    acc[i][j] = fmaf(qv[i].y, kv[j].y, acc[i][j]);
                }
        }
        #pragma unroll
        for (int i = 0; i < 4; i++)
            #pragma unroll
            for (int j = 0; j < 4; j++)
                sc[(h*16 + tg*4 + i)*64 + sg*4 + j] = acc[i][j] * 0.125f;
    }
    __syncthreads();

    {
        int warp = tid >> 5, lane = tid & 31;
        for (int r = warp; r < 48; r += 8) {
            float v0 = sc[r*64 + lane], v1 = sc[r*64 + 32 + lane];
            float mx = fmaxf(v0, v1);
            #pragma unroll
            for (int o = 16; o > 0; o >>= 1)
                mx = fmaxf(mx, __shfl_xor_sync(0xffffffffu, mx, o));
            float e0 = expf(v0 - mx), e1 = expf(v1 - mx);
            float ss = e0 + e1;
            #pragma unroll
            for (int o = 16; o > 0; o >>= 1)
                ss += __shfl_xor_sync(0xffffffffu, ss, o);
            float inv = 1.f / ss;
            sc[r*64 + lane]      = e0 * inv;
            sc[r*64 + 32 + lane] = e1 * inv;
        }
    }
    __syncthreads();

    if (tid < 192) {
        int dg = tid & 15, tg = (tid >> 4) & 3, h = tid >> 6;
        float acc[4][4] = {};
        const uint32_t* vhw = reinterpret_cast<const uint32_t*>(vh);
        #pragma unroll 4
        for (int s2 = 0; s2 < 32; s2++) {
            float2 pv[4], vv[4];
            #pragma unroll
            for (int i = 0; i < 4; i++) {
                pv[i] = *reinterpret_cast<const float2*>(&sc[(h*16 + tg*4 + i)*64 + s2*2]);
                uint32_t vw = vhw[(h*64 + dg*4 + i)*33 + s2];
                vv[i] = __bfloat1622float2(*reinterpret_cast<__nv_bfloat162*>(&vw));
            }
            #pragma unroll
            for (int i = 0; i < 4; i++)
                #pragma unroll
                for (int j = 0; j < 4; j++) {
                    acc[i][j] = fmaf(pv[i].x, vv[j].x, acc[i][j]);
                    acc[i][j] = fmaf(pv[i].y, vv[j].y, acc[i][j]);
                }
        }
        #pragma unroll
        for (int i = 0; i < 4; i++) {
            int t2 = tg*4 + i;
            size_t orow = ((size_t)(b*128 + wi*4 + (t2 >> 2)))*128 + wj*4 + (t2 & 3);
            size_t off = orow*192 + h*64 + dg*4;
            #pragma unroll
            for (int j = 0; j < 4; j += 2)
                *reinterpret_cast<__half2*>(O + off + j) =
                    __floats2half2_rn(acc[i][j], acc[i][j+1]);
        }
    }
}

// ---------------- launch ----------------------------------------------------
extern "C" void kernel_launch(void* const* d_in, const int* in_sizes, int n_in,
                              void* d_out, int out_size)
{
    const float* x       = (const float*)d_in[0];
    const float* n1g     = (const float*)d_in[1];
    const float* n1b     = (const float*)d_in[2];
    const float* proj_w  = (const float*)d_in[3];
    const float* proj_b  = (const float*)d_in[4];
    const float* qkv_w   = (const float*)d_in[5];
    const float* qkv_b   = (const float*)d_in[6];
    const float* apw     = (const float*)d_in[7];
    const float* apb     = (const float*)d_in[8];
    const float* n2g     = (const float*)d_in[9];
    const float* n2b     = (const float*)d_in[10];
    const float* w1      = (const float*)d_in[11];
    const float* b1      = (const float*)d_in[12];
    const float* w2      = (const float*)d_in[13];
    const float* b2      = (const float*)d_in[14];
    float* y = (float*)d_out;

    __nv_bfloat16 *xh, *xl, *qkvb, *wfh, *wfl;
    __half *o16, *yn16, *h16, *wa16, *w116, *w216;
    float *b768;
    cudaGetSymbolAddress((void**)&xh,  g_xh);
    cudaGetSymbolAddress((void**)&xl,  g_xl);
    cudaGetSymbolAddress((void**)&qkvb, g_qkvb);
    cudaGetSymbolAddress((void**)&o16, g_o);
    cudaGetSymbolAddress((void**)&yn16, g_yn);
    cudaGetSymbolAddress((void**)&h16, g_h);
    cudaGetSymbolAddress((void**)&wfh, g_wfh);
    cudaGetSymbolAddress((void**)&wfl, g_wfl);
    cudaGetSymbolAddress((void**)&wa16, g_wa16);
    cudaGetSymbolAddress((void**)&w116, g_w116);
    cudaGetSymbolAddress((void**)&w216, g_w216);
    cudaGetSymbolAddress((void**)&b768, g_b768);

    static bool attr_done = false;
    if (!attr_done) {
        cudaFuncSetAttribute(attn_kernel,
            cudaFuncAttributeMaxDynamicSharedMemorySize, ATT_SMEM);
        cudaFuncSetAttribute(gemm_fused,
            cudaFuncAttributeMaxDynamicSharedMemorySize, GEMM_SMEM);
        cudaFuncSetAttribute(gemm_f16,
            cudaFuncAttributeMaxDynamicSharedMemorySize, GEMMH_SMEM);
        attr_done = true;
    }

    // 0) merged weight conversions + bias concat
    conv_all_kernel<<<(406272 + 255) / 256, 256>>>(
        proj_w, qkv_w, apw, w1, w2, proj_b, qkv_b,
        wfh, wfl, wa16, w116, w216, b768);
    // 1) LN1 -> bf16 hi/lo (window-major rows)
    ln96b_kernel<<<NPIX/8, 256>>>(x, n1g, n1b, xh, xl);
    // 2) fused proj+qkv GEMM: tile0 (x3) -> pooled y, tiles1-3 (x1) -> qkv bf16
    gemm_fused<<<dim3(4, NPIX/128), 256, GEMM_SMEM>>>(
        xh, xl, wfh, wfl, b768, y, qkvb);
    // 3) windowed attention -> O (fp16)
    attn_kernel<<<NWIN, 256, ATT_SMEM>>>(qkvb, o16);
    // 4) attn-proj GEMM (fp16 x1): y += O @ apw + apb
    gemm_f16<<<dim3(1, NPOOL/128), 256, GEMMH_SMEM>>>(
        o16, wa16, 192, 192, 2, apb, y, nullptr, y);
    // 5) LN2 -> fp16
    ln192h_kernel<<<NPOOL/8, 256>>>(y, n2g, n2b, yn16);
    // 6) mlp1 GEMM (fp16 x1) + gelu -> h (fp16)
    gemm_f16<<<dim3(4, NPOOL/128), 256, GEMMH_SMEM>>>(
        yn16, w116, 192, 768, 1, b1, nullptr, h16, nullptr);
    // 7) mlp2 GEMM (fp16 x1) + residual add -> y (d_out)
    gemm_f16<<<dim3(1, NPOOL/128), 256, GEMMH_SMEM>>>(
        h16, w216, 768, 192, 2, b2, y, nullptr, y);
}

// round 12
// speedup vs baseline: 1.8079x; 1.3981x over previous
#include <cuda_runtime.h>
#include <cuda_bf16.h>
#include <cuda_fp16.h>
#include <cstdint>
#include <math.h>

// ===========================================================================
// MultiScaleBlock (sm_103 PTX, HMMA mma.sync path).
// All GEMMs fp16 x1 (fused proj+qkv with maxpool epilogue; attn-proj; mlp).
// Window-major pixel permutation; attention: fp16x2-packed smem, 4x4 reg
// blocking, 3 CTAs/SM.
// ===========================================================================

#define NPIX   (4*256*256)     // 262144
#define NPOOL  (4*128*128)     // 65536
#define NWIN   (4*32*32)       // 4096

// ---------------- scratch (device globals) ----------------------------------
__device__ __half g_x16 [(size_t)NPIX  * 96];    // LN1 out, window-major fp16
__device__ __half g_qkv [(size_t)NPIX  * 576];   // qkv fp16, window-major
__device__ __half g_o   [(size_t)NPOOL * 192];   // attention O
__device__ __half g_yn  [(size_t)NPOOL * 192];   // LN2 out
__device__ __half g_h   [(size_t)NPOOL * 768];   // mlp hidden
// weights fp16 [N][K] (transposed); proj+qkv fused into 768 rows
__device__ __half g_wf16[768*96];
__device__ __half g_wa16[192*192];
__device__ __half g_w116[768*192];
__device__ __half g_w216[192*768];
__device__ float  g_b768[768];

// ---------------- helpers ---------------------------------------------------
__device__ __forceinline__ uint32_t smem_u32(const void* p) {
    uint32_t a;
    asm("{ .reg .u64 t; cvta.to.shared.u64 t, %1; cvt.u32.u64 %0, t; }"
        : "=r"(a) : "l"(p));
    return a;
}
__device__ __forceinline__ void cp16(uint32_t s, const void* g) {
    asm volatile("cp.async.ca.shared.global [%0], [%1], 16;"
                 :: "r"(s), "l"(g) : "memory");
}
__device__ __forceinline__ void cp_commit() {
    asm volatile("cp.async.commit_group;" ::: "memory");
}
template<int N>
__device__ __forceinline__ void cp_wait() {
    asm volatile("cp.async.wait_group %0;" :: "n"(N) : "memory");
}
__device__ __forceinline__ void ldsm4(uint32_t* r, uint32_t a) {
    asm volatile("ldmatrix.sync.aligned.m8n8.x4.shared.b16 {%0,%1,%2,%3}, [%4];"
        : "=r"(r[0]), "=r"(r[1]), "=r"(r[2]), "=r"(r[3]) : "r"(a));
}
__device__ __forceinline__ void mma_fp16(float* d, const uint32_t* a,
                                         uint32_t b0, uint32_t b1) {
    asm volatile(
        "mma.sync.aligned.m16n8k16.row.col.f32.f16.f16.f32 "
        "{%0,%1,%2,%3}, {%4,%5,%6,%7}, {%8,%9}, {%0,%1,%2,%3};"
        : "+f"(d[0]), "+f"(d[1]), "+f"(d[2]), "+f"(d[3])
        : "r"(a[0]), "r"(a[1]), "r"(a[2]), "r"(a[3]), "r"(b0), "r"(b1));
}
__device__ __forceinline__ float gelu_exact(float v) {
    return 0.5f * v * (1.0f + erff(v * 0.70710678118654752f));
}
// window-major quad index -> standard pooled row
__device__ __forceinline__ size_t quad_to_prow(size_t g) {
    int t2 = (int)(g & 15);
    int wj = (int)((g >> 4) & 31);
    int wi = (int)((g >> 9) & 31);
    int b  = (int)(g >> 14);
    return ((size_t)(b * 128 + wi * 4 + (t2 >> 2))) * 128 + wj * 4 + (t2 & 3);
}

// ======== fp16 x1 GEMM, BM=128 BN=192 BK=32, 3-stage, 2 CTA/SM ==============
// epi: 1 = gelu -> fp16; 2 = +bias +addsrc -> fp32;
//      3 = fused: bn==0 -> pooled maxpool into y (fp32), bn>0 -> qkv fp16 ld576
#define LDAH     40
#define SAH      0
#define SBH      (128*LDAH*2)               // 10240
#define STAGEH   (SBH + 192*LDAH*2)         // 25600
#define GEMMH_SMEM (3*STAGEH)               // 76800

__global__ __launch_bounds__(256, 2) void gemm_f16(
    const __half* __restrict__ A, const __half* __restrict__ B,
    int K, int N, int epi,
    const float* __restrict__ bias,
    float* __restrict__ Cf, __half* __restrict__ Ch,
    const float* __restrict__ addsrc)
{
    extern __shared__ char smem[];
    const uint32_t sb = smem_u32(smem);
    const int tid = threadIdx.x, lane = tid & 31, warp = tid >> 5;
    const int wm = (warp >> 1) * 32;
    const int wn = (warp & 1) * 96;
    const size_t bm = (size_t)blockIdx.y * 128;
    const size_t bn = (size_t)blockIdx.x * 192;
    const int C = K >> 5;

    const __half* AB = A + bm * K;
    const __half* BB = B + bn * K;

    float acc[2][12][4];
    #pragma unroll
    for (int i = 0; i < 2; i++)
        #pragma unroll
        for (int j = 0; j < 12; j++)
            #pragma unroll
            for (int q = 0; q < 4; q++) acc[i][j][q] = 0.f;

    auto load_stage = [&](int s, int c) {
        const uint32_t st = sb + (uint32_t)s * STAGEH;
        const size_t k0 = (size_t)c * 32;
        #pragma unroll
        for (int i = tid; i < 512; i += 256) {
            int r = i >> 2, q = i & 3;
            cp16(st + SAH + (uint32_t)(r * LDAH + q * 8) * 2,
                 AB + (size_t)r * K + k0 + q * 8);
        }
        #pragma unroll
        for (int i = tid; i < 768; i += 256) {
            int r = i >> 2, q = i & 3;
            cp16(st + SBH + (uint32_t)(r * LDAH + q * 8) * 2,
                 BB + (size_t)r * K + k0 + q * 8);
        }
        cp_commit();
    };

    auto compute_stage = [&](int s) {
        const uint32_t st = sb + (uint32_t)s * STAGEH;
        #pragma unroll
        for (int k16 = 0; k16 < 2; k16++) {
            uint32_t ah[2][4];
            #pragma unroll
            for (int mi = 0; mi < 2; mi++) {
                int row = wm + mi * 16 + (lane & 15);
                int col = k16 * 16 + (lane >> 4) * 8;
                ldsm4(ah[mi], st + SAH + (uint32_t)(row * LDAH + col) * 2);
            }
            #pragma unroll
            for (int ng = 0; ng < 6; ng++) {
                uint32_t bh[4];
                int nr = wn + ng * 16 + (lane & 7) + ((lane >> 4) & 1) * 8;
                int bc = k16 * 16 + ((lane >> 3) & 1) * 8;
                ldsm4(bh, st + SBH + (uint32_t)(nr * LDAH + bc) * 2);
                #pragma unroll
                for (int mi = 0; mi < 2; mi++) {
                    #pragma unroll
                    for (int sub = 0; sub < 2; sub++)
                        mma_fp16(acc[mi][ng * 2 + sub], ah[mi], bh[2*sub], bh[2*sub+1]);
                }
            }
        }
    };

    load_stage(0, 0);
    load_stage(1, 1);
    for (int c = 0; c < C; c++) {
        if (c + 1 < C) { cp_wait<1>(); } else { cp_wait<0>(); }
        __syncthreads();
        if (c + 2 < C) load_stage((c + 2) % 3, c + 2);
        compute_stage(c % 3);
        __syncthreads();
    }

    #pragma unroll
    for (int mi = 0; mi < 2; mi++) {
        #pragma unroll
        for (int nj = 0; nj < 12; nj++) {
            size_t row0 = bm + wm + mi * 16 + (lane >> 2);
            size_t col  = bn + wn + nj * 8 + 2 * (lane & 3);
            float b0 = bias[col], b1 = bias[col + 1];
            float v00 = acc[mi][nj][0] + b0, v01 = acc[mi][nj][1] + b1;
            float v10 = acc[mi][nj][2] + b0, v11 = acc[mi][nj][3] + b1;
            if (epi == 1) {
                v00 = gelu_exact(v00); v01 = gelu_exact(v01);
                v10 = gelu_exact(v10); v11 = gelu_exact(v11);
                *reinterpret_cast<__half2*>(Ch + row0 * N + col)       = __floats2half2_rn(v00, v01);
                *reinterpret_cast<__half2*>(Ch + (row0 + 8) * N + col) = __floats2half2_rn(v10, v11);
            } else if (epi == 2) {
                const float2 a0 = *reinterpret_cast<const float2*>(addsrc + row0 * N + col);
                const float2 a1 = *reinterpret_cast<const float2*>(addsrc + (row0 + 8) * N + col);
                *reinterpret_cast<float2*>(Cf + row0 * N + col)       = make_float2(v00 + a0.x, v01 + a0.y);
                *reinterpret_cast<float2*>(Cf + (row0 + 8) * N + col) = make_float2(v10 + a1.x, v11 + a1.y);
            } else {  // epi == 3
                if (bn == 0) {
                    float p00 = fmaxf(v00, __shfl_xor_sync(0xffffffffu, v00, 4));
                    p00 = fmaxf(p00, __shfl_xor_sync(0xffffffffu, p00, 8));
                    float p01 = fmaxf(v01, __shfl_xor_sync(0xffffffffu, v01, 4));
                    p01 = fmaxf(p01, __shfl_xor_sync(0xffffffffu, p01, 8));
                    float p10 = fmaxf(v10, __shfl_xor_sync(0xffffffffu, v10, 4));
                    p10 = fmaxf(p10, __shfl_xor_sync(0xffffffffu, p10, 8));
                    float p11 = fmaxf(v11, __shfl_xor_sync(0xffffffffu, v11, 4));
                    p11 = fmaxf(p11, __shfl_xor_sync(0xffffffffu, p11, 8));
                    if ((lane & 12) == 0) {
                        size_t pr0 = quad_to_prow(row0 >> 2);
                        size_t pr1 = quad_to_prow((row0 + 8) >> 2);
                        *reinterpret_cast<float2*>(Cf + pr0 * 192 + col) = make_float2(p00, p01);
                        *reinterpret_cast<float2*>(Cf + pr1 * 192 + col) = make_float2(p10, p11);
                    }
                } else {
                    size_t qc = col - 192;
                    *reinterpret_cast<__half2*>(Ch + row0 * 576 + qc)       = __floats2half2_rn(v00, v01);
                    *reinterpret_cast<__half2*>(Ch + (row0 + 8) * 576 + qc) = __floats2half2_rn(v10, v11);
                }
            }
        }
    }
}

// ---------------- LN1 -> fp16, window-major permuted rows -------------------
__global__ __launch_bounds__(256) void ln96h_kernel(
    const float* __restrict__ x, const float* __restrict__ g,
    const float* __restrict__ bb, __half* __restrict__ out)
{
    int row  = blockIdx.x * 8 + (threadIdx.x >> 5);
    int lane = threadIdx.x & 31;
    const float* p = x + (size_t)row * 96;
    float v0 = p[lane], v1 = p[lane+32], v2 = p[lane+64];
    float s = v0 + v1 + v2;
    #pragma unroll
    for (int o = 16; o > 0; o >>= 1) s += __shfl_xor_sync(0xffffffffu, s, o);
    float mean = s * (1.0f/96.0f);
    float d0 = v0-mean, d1 = v1-mean, d2 = v2-mean;
    float vs = d0*d0 + d1*d1 + d2*d2;
    #pragma unroll
    for (int o = 16; o > 0; o >>= 1) vs += __shfl_xor_sync(0xffffffffu, vs, o);
    float inv = rsqrtf(vs * (1.0f/96.0f) + 1e-6f);
    int wpix = row & 255, hpix = (row >> 8) & 255, b = row >> 16;
    int wi = hpix >> 3, r = hpix & 7, wj = wpix >> 3, c = wpix & 7;
    int t2 = (r >> 1) * 4 + (c >> 1);
    int dq = (r & 1) * 2 + (c & 1);
    size_t wrow = ((((size_t)b * 32 + wi) * 32 + wj) * 16 + t2) * 4 + dq;
    __half* q = out + wrow * 96;
    q[lane]    = __float2half(d0*inv*g[lane]    + bb[lane]);
    q[lane+32] = __float2half(d1*inv*g[lane+32] + bb[lane+32]);
    q[lane+64] = __float2half(d2*inv*g[lane+64] + bb[lane+64]);
}

// ---------------- LN2 -> fp16 -----------------------------------------------
__global__ __launch_bounds__(256) void ln192h_kernel(
    const float* __restrict__ x, const float* __restrict__ g,
    const float* __restrict__ bb, __half* __restrict__ out)
{
    int row  = blockIdx.x * 8 + (threadIdx.x >> 5);
    int lane = threadIdx.x & 31;
    const float* p = x + (size_t)row * 192;
    float v[6];
    float s = 0.f;
    #pragma unroll
    for (int i = 0; i < 6; i++) { v[i] = p[lane + 32*i]; s += v[i]; }
    #pragma unroll
    for (int o = 16; o > 0; o >>= 1) s += __shfl_xor_sync(0xffffffffu, s, o);
    float mean = s * (1.0f/192.0f);
    float vs = 0.f;
    #pragma unroll
    for (int i = 0; i < 6; i++) { v[i] -= mean; vs += v[i]*v[i]; }
    #pragma unroll
    for (int o = 16; o > 0; o >>= 1) vs += __shfl_xor_sync(0xffffffffu, vs, o);
    float inv = rsqrtf(vs * (1.0f/192.0f) + 1e-6f);
    __half* q = out + (size_t)row * 192;
    #pragma unroll
    for (int i = 0; i < 6; i++)
        q[lane + 32*i] = __float2half(v[i]*inv*g[lane + 32*i] + bb[lane + 32*i]);
}

// ---------------- merged weight conversion + bias concat --------------------
__global__ __launch_bounds__(256) void conv_all_kernel(
    const float* __restrict__ proj_w, const float* __restrict__ qkv_w,
    const float* __restrict__ apw, const float* __restrict__ w1,
    const float* __restrict__ w2,
    const float* __restrict__ proj_b, const float* __restrict__ qkv_b,
    __half* __restrict__ wf16, __half* __restrict__ wa16,
    __half* __restrict__ w116, __half* __restrict__ w216,
    float* __restrict__ b768)
{
    int i = blockIdx.x * 256 + threadIdx.x;
    if (i < 405504) {
        const float* W; __half* H; int K, N, j;
        if (i < 18432)       { W = proj_w; H = wf16;         K = 96;  N = 192; j = i; }
        else if (i < 73728)  { W = qkv_w;  H = wf16 + 18432; K = 96;  N = 576; j = i - 18432; }
        else if (i < 110592) { W = apw;    H = wa16;         K = 192; N = 192; j = i - 73728; }
        else if (i < 258048) { W = w1;     H = w116;         K = 192; N = 768; j = i - 110592; }
        else                 { W = w2;     H = w216;         K = 768; N = 192; j = i - 258048; }
        int n = j / K, k = j % K;
        H[j] = __float2half(W[(size_t)k * N + n]);
    } else if (i < 406272) {
        int j = i - 405504;
        b768[j] = (j < 192) ? proj_b[j] : qkv_b[j - 192];
    }
}

// ---------------- windowed attention (fp16 qkv): 4x4 reg blocking -----------
// smem (words): qp [16][100] | kh [3][64][35] | vh fp16 [3][64][66] | sc [3][16][64]
#define ATT_SMEM 70912

__global__ __launch_bounds__(256, 3) void attn_kernel(
    const __half* __restrict__ qkv, __half* __restrict__ O)
{
    extern __shared__ float sm[];
    uint32_t* qp = reinterpret_cast<uint32_t*>(sm);
    uint32_t* kh = qp + 1600;
    __half* vh = reinterpret_cast<__half*>(kh + 6720);
    float* sc = sm + 14656;

    int w = blockIdx.x;
    int b = w >> 10, wi = (w >> 5) & 31, wj = w & 31;
    int tid = threadIdx.x;
    const uint32_t* qk = reinterpret_cast<const uint32_t*>(qkv + (size_t)w * 64 * 576);

    // 1) pooled q (max over quad), packed fp16x2
    for (int i = tid; i < 16*96; i += 256) {
        int t2 = i / 96, c2 = i % 96;
        float m0 = -1e30f, m1 = -1e30f;
        #pragma unroll
        for (int dq = 0; dq < 4; dq++) {
            uint32_t wd = qk[(t2*4 + dq)*288 + c2];
            float2 v = __half22float2(*reinterpret_cast<__half2*>(&wd));
            m0 = fmaxf(m0, v.x);
            m1 = fmaxf(m1, v.y);
        }
        __half2 r = __floats2half2_rn(m0, m1);
        qp[t2*100 + c2] = *reinterpret_cast<uint32_t*>(&r);
    }
    // 2) k packed rows; v transposed to [d][s] fp16
    for (int i = tid; i < 3*64*32; i += 256) {
        int d2 = i & 31, s = (i >> 5) & 63, h = i >> 11;
        kh[(h*64 + s)*35 + d2] = qk[s*288 + 96 + h*32 + d2];
        uint32_t vw = qk[s*288 + 192 + h*32 + d2];
        __half2 vv = *reinterpret_cast<__half2*>(&vw);
        vh[(h*64 + d2*2    )*66 + s] = vv.x;
        vh[(h*64 + d2*2 + 1)*66 + s] = vv.y;
    }
    __syncthreads();

    // 3) scores
    if (tid < 192) {
        int sg = tid & 15, tg = (tid >> 4) & 3, h = tid >> 6;
        float acc[4][4] = {};
        #pragma unroll 4
        for (int d2 = 0; d2 < 32; d2++) {
            float2 qv[4], kv[4];
            #pragma unroll
            for (int i = 0; i < 4; i++) {
                uint32_t qw = qp[(tg*4 + i)*100 + h*32 + d2];
                qv[i] = __half22float2(*reinterpret_cast<__half2*>(&qw));
                uint32_t kw = kh[(h*64 + sg*4 + i)*35 + d2];
                kv[i] = __half22float2(*reinterpret_cast<__half2*>(&kw));
            }
            #pragma unroll
            for (int i = 0; i < 4; i++)
                #pragma unroll
                for (int j = 0; j < 4; j++) {
                    acc[i][j] = fmaf(qv[i].x, kv[j].x, acc[i][j]);
                    acc[i][j] = fmaf(qv[i].y, kv[j].y, acc[i][j]);
                }
        }
        #pragma unroll
        for (int i = 0; i < 4; i++)
            #pragma unroll
            for (int j = 0; j < 4; j++)
                sc[(h*16 + tg*4 + i)*64 + sg*4 + j] = acc[i][j] * 0.125f;
    }
    __syncthreads();

    // 4) softmax
    {
        int warp = tid >> 5, lane = tid & 31;
        for (int r = warp; r < 48; r += 8) {
            float v0 = sc[r*64 + lane], v1 = sc[r*64 + 32 + lane];
            float mx = fmaxf(v0, v1);
            #pragma unroll
            for (int o = 16; o > 0; o >>= 1)
                mx = fmaxf(mx, __shfl_xor_sync(0xffffffffu, mx, o));
            float e0 = expf(v0 - mx), e1 = expf(v1 - mx);
            float ss = e0 + e1;
            #pragma unroll
            for (int o = 16; o > 0; o >>= 1)
                ss += __shfl_xor_sync(0xffffffffu, ss, o);
            float inv = 1.f / ss;
            sc[r*64 + lane]      = e0 * inv;
            sc[r*64 + 32 + lane] = e1 * inv;
        }
    }
    __syncthreads();

    // 5) out
    if (tid < 192) {
        int dg = tid & 15, tg = (tid >> 4) & 3, h = tid >> 6;
        float acc[4][4] = {};
        const uint32_t* vhw = reinterpret_cast<const uint32_t*>(vh);
        #pragma unroll 4
        for (int s2 = 0; s2 < 32; s2++) {
            float2 pv[4], vv[4];
            #pragma unroll
            for (int i = 0; i < 4; i++) {
                pv[i] = *reinterpret_cast<const float2*>(&sc[(h*16 + tg*4 + i)*64 + s2*2]);
                uint32_t vw = vhw[(h*64 + dg*4 + i)*33 + s2];
                vv[i] = __half22float2(*reinterpret_cast<__half2*>(&vw));
            }
            #pragma unroll
            for (int i = 0; i < 4; i++)
                #pragma unroll
                for (int j = 0; j < 4; j++) {
                    acc[i][j] = fmaf(pv[i].x, vv[j].x, acc[i][j]);
                    acc[i][j] = fmaf(pv[i].y, vv[j].y, acc[i][j]);
                }
        }
        #pragma unroll
        for (int i = 0; i < 4; i++) {
            int t2 = tg*4 + i;
            size_t orow = ((size_t)(b*128 + wi*4 + (t2 >> 2)))*128 + wj*4 + (t2 & 3);
            size_t off = orow*192 + h*64 + dg*4;
            #pragma unroll
            for (int j = 0; j < 4; j += 2)
                *reinterpret_cast<__half2*>(O + off + j) =
                    __floats2half2_rn(acc[i][j], acc[i][j+1]);
        }
    }
}

// ---------------- launch ----------------------------------------------------
extern "C" void kernel_launch(void* const* d_in, const int* in_sizes, int n_in,
                              void* d_out, int out_size)
{
    const float* x       = (const float*)d_in[0];
    const float* n1g     = (const float*)d_in[1];
    const float* n1b     = (const float*)d_in[2];
    const float* proj_w  = (const float*)d_in[3];
    const float* proj_b  = (const float*)d_in[4];
    const float* qkv_w   = (const float*)d_in[5];
    const float* qkv_b   = (const float*)d_in[6];
    const float* apw     = (const float*)d_in[7];
    const float* apb     = (const float*)d_in[8];
    const float* n2g     = (const float*)d_in[9];
    const float* n2b     = (const float*)d_in[10];
    const float* w1      = (const float*)d_in[11];
    const float* b1      = (const float*)d_in[12];
    const float* w2      = (const float*)d_in[13];
    const float* b2      = (const float*)d_in[14];
    float* y = (float*)d_out;

    __half *x16, *qkv16, *o16, *yn16, *h16, *wf16, *wa16, *w116, *w216;
    float *b768;
    cudaGetSymbolAddress((void**)&x16,  g_x16);
    cudaGetSymbolAddress((void**)&qkv16, g_qkv);
    cudaGetSymbolAddress((void**)&o16,  g_o);
    cudaGetSymbolAddress((void**)&yn16, g_yn);
    cudaGetSymbolAddress((void**)&h16,  g_h);
    cudaGetSymbolAddress((void**)&wf16, g_wf16);
    cudaGetSymbolAddress((void**)&wa16, g_wa16);
    cudaGetSymbolAddress((void**)&w116, g_w116);
    cudaGetSymbolAddress((void**)&w216, g_w216);
    cudaGetSymbolAddress((void**)&b768, g_b768);

    static bool attr_done = false;
    if (!attr_done) {
        cudaFuncSetAttribute(attn_kernel,
            cudaFuncAttributeMaxDynamicSharedMemorySize, ATT_SMEM);
        cudaFuncSetAttribute(gemm_f16,
            cudaFuncAttributeMaxDynamicSharedMemorySize, GEMMH_SMEM);
        attr_done = true;
    }

    // 0) merged weight conversions + bias concat
    conv_all_kernel<<<(406272 + 255) / 256, 256>>>(
        proj_w, qkv_w, apw, w1, w2, proj_b, qkv_b,
        wf16, wa16, w116, w216, b768);
    // 1) LN1 -> fp16 (window-major rows)
    ln96h_kernel<<<NPIX/8, 256>>>(x, n1g, n1b, x16);
    // 2) fused proj+qkv GEMM: tile0 -> pooled y, tiles1-3 -> qkv fp16
    gemm_f16<<<dim3(4, NPIX/128), 256, GEMMH_SMEM>>>(
        x16, wf16, 96, 768, 3, b768, y, qkv16, nullptr);
    // 3) windowed attention -> O (fp16)
    attn_kernel<<<NWIN, 256, ATT_SMEM>>>(qkv16, o16);
    // 4) attn-proj GEMM: y += O @ apw + apb
    gemm_f16<<<dim3(1, NPOOL/128), 256, GEMMH_SMEM>>>(
        o16, wa16, 192, 192, 2, apb, y, nullptr, y);
    // 5) LN2 -> fp16
    ln192h_kernel<<<NPOOL/8, 256>>>(y, n2g, n2b, yn16);
    // 6) mlp1 GEMM + gelu -> h (fp16)
    gemm_f16<<<dim3(4, NPOOL/128), 256, GEMMH_SMEM>>>(
        yn16, w116, 192, 768, 1, b1, nullptr, h16, nullptr);
    // 7) mlp2 GEMM + residual add -> y (d_out)
    gemm_f16<<<dim3(1, NPOOL/128), 256, GEMMH_SMEM>>>(
        h16, w216, 768, 192, 2, b2, y, nullptr, y);
}